// round 1
// baseline (speedup 1.0000x reference)
#include <cuda_runtime.h>
#include <cstdio>

// Problem constants
#define NHEADS 16
#define HDIM   64
#define BATCH  4
#define SEQ    2048
#define CDIM   1024
#define MTOT   (BATCH * SEQ)          // 8192
#define N3     (3 * CDIM)             // 3072

// Scratch (allocation-free rule: __device__ globals)
__device__ float g_qkv[(size_t)MTOT * N3];                    // 96 MB
__device__ float g_q[(size_t)BATCH * NHEADS * SEQ * HDIM];    // 32 MB
__device__ float g_k[(size_t)BATCH * NHEADS * SEQ * HDIM];    // 32 MB
__device__ float g_v[(size_t)BATCH * NHEADS * SEQ * HDIM];    // 32 MB
__device__ float g_attn[(size_t)MTOT * CDIM];                 // 32 MB

// ---------------------------------------------------------------------------
// SGEMM (NT): C[m,n] = sum_k A[m,k] * W[n,k] + bias[n]
// A row-major [M,K], W row-major [N,K]. 128x128 tile, BK=8, 256 thr, 8x8/thr.
// ---------------------------------------------------------------------------
__global__ __launch_bounds__(256, 2) void sgemm_nt_bias(
    const float* __restrict__ A, const float* __restrict__ W,
    const float* __restrict__ bias, float* __restrict__ C,
    int M, int N, int K)
{
    __shared__ float As[8][128];
    __shared__ float Bs[8][128];

    const int tid = threadIdx.x;
    const int tx = tid & 15;
    const int ty = tid >> 4;
    const int bm = blockIdx.y * 128;
    const int bn = blockIdx.x * 128;

    const int lr = tid >> 1;          // 0..127
    const int lk = (tid & 1) * 4;     // 0 or 4

    const float* Ap = A + (size_t)(bm + lr) * K + lk;
    const float* Wp = W + (size_t)(bn + lr) * K + lk;

    float acc[8][8];
#pragma unroll
    for (int i = 0; i < 8; i++)
#pragma unroll
        for (int j = 0; j < 8; j++) acc[i][j] = 0.f;

    float4 av = *(const float4*)Ap;
    float4 bv = *(const float4*)Wp;

    for (int kt = 0; kt < K; kt += 8) {
        __syncthreads();
        As[lk + 0][lr] = av.x; As[lk + 1][lr] = av.y;
        As[lk + 2][lr] = av.z; As[lk + 3][lr] = av.w;
        Bs[lk + 0][lr] = bv.x; Bs[lk + 1][lr] = bv.y;
        Bs[lk + 2][lr] = bv.z; Bs[lk + 3][lr] = bv.w;
        __syncthreads();
        if (kt + 8 < K) {
            av = *(const float4*)(Ap + kt + 8);
            bv = *(const float4*)(Wp + kt + 8);
        }
#pragma unroll
        for (int k = 0; k < 8; k++) {
            float a[8], b[8];
            *(float4*)&a[0] = *(const float4*)&As[k][ty * 4];
            *(float4*)&a[4] = *(const float4*)&As[k][ty * 4 + 64];
            *(float4*)&b[0] = *(const float4*)&Bs[k][tx * 4];
            *(float4*)&b[4] = *(const float4*)&Bs[k][tx * 4 + 64];
#pragma unroll
            for (int i = 0; i < 8; i++)
#pragma unroll
                for (int j = 0; j < 8; j++)
                    acc[i][j] += a[i] * b[j];
        }
    }

    const float4 bias0 = *(const float4*)&bias[bn + tx * 4];
    const float4 bias1 = *(const float4*)&bias[bn + tx * 4 + 64];
#pragma unroll
    for (int i = 0; i < 8; i++) {
        int r = bm + ty * 4 + i + ((i >= 4) ? 60 : 0);
        float4 o0, o1;
        o0.x = acc[i][0] + bias0.x; o0.y = acc[i][1] + bias0.y;
        o0.z = acc[i][2] + bias0.z; o0.w = acc[i][3] + bias0.w;
        o1.x = acc[i][4] + bias1.x; o1.y = acc[i][5] + bias1.y;
        o1.z = acc[i][6] + bias1.z; o1.w = acc[i][7] + bias1.w;
        *(float4*)&C[(size_t)r * N + bn + tx * 4]      = o0;
        *(float4*)&C[(size_t)r * N + bn + tx * 4 + 64] = o1;
    }
}

// ---------------------------------------------------------------------------
// RoPE + split qkv[m, 3*1024] into head-major q/k/v [b,h,s,d]
// ---------------------------------------------------------------------------
__global__ __launch_bounds__(256) void rope_split_kernel(
    const float* __restrict__ qkv, const float* __restrict__ cosb,
    const float* __restrict__ sinb, float* __restrict__ q,
    float* __restrict__ k, float* __restrict__ v)
{
    int idx = blockIdx.x * 256 + threadIdx.x;   // over MTOT * CDIM
    if (idx >= MTOT * CDIM) return;
    int m  = idx >> 10;          // 0..8191 (= b*SEQ + s)
    int hd = idx & 1023;
    int b  = m >> 11;
    int s  = m & 2047;
    int h  = hd >> 6;
    int d  = hd & 63;

    const float* row = qkv + (size_t)m * N3;
    float cs = cosb[(size_t)m * HDIM + d];
    float sn = sinb[(size_t)m * HDIM + d];
    size_t oidx = (((size_t)(b * NHEADS + h) * SEQ) + s) * HDIM + d;

    float xq = row[hd];
    float rq = (d < 32) ? -row[hd + 32] : row[hd - 32];
    q[oidx] = xq * cs + rq * sn;

    float xk = row[CDIM + hd];
    float rk = (d < 32) ? -row[CDIM + hd + 32] : row[CDIM + hd - 32];
    k[oidx] = xk * cs + rk * sn;

    v[oidx] = row[2 * CDIM + hd];
}

// ---------------------------------------------------------------------------
// Flash attention, fp32. Block = 128 queries; loop over 128-key tiles.
// 256 threads, each owns 8 rows x 8 score cols / 8 rows x 4 out cols.
// Q,K staged transposed [d][row] (stride 132); V natural [c][d] (stride 68);
// P staged transposed [c][r] (stride 129).
// ---------------------------------------------------------------------------
#define QK_ST 132
#define V_ST  68
#define P_ST  129
#define ATTN_SMEM_FLOATS (2 * 64 * QK_ST + 128 * V_ST + 128 * P_ST)  // 42112
#define ATTN_SMEM_BYTES  (ATTN_SMEM_FLOATS * 4)                       // 168448

__global__ __launch_bounds__(256, 1) void attn_kernel(
    const float* __restrict__ Q, const float* __restrict__ K,
    const float* __restrict__ V, float* __restrict__ Out)
{
    extern __shared__ float smf[];
    float* Qs = smf;                        // 64 * 132
    float* Ks = smf + 64 * QK_ST;           // 64 * 132
    float* Vs = smf + 2 * 64 * QK_ST;       // 128 * 68
    float* Ps = smf + 2 * 64 * QK_ST + 128 * V_ST;   // 128 * 129

    const int tid = threadIdx.x;
    const int tx  = tid & 15;
    const int ty  = tid >> 4;
    const int qt  = blockIdx.x;             // query tile (16 of them)
    const int bh  = blockIdx.y;             // 0..63
    const int b   = bh >> 4;
    const int h   = bh & 15;

    const float* Qbase = Q + ((size_t)bh * SEQ + (size_t)qt * 128) * HDIM;
    const float* Kbase = K + (size_t)bh * SEQ * HDIM;
    const float* Vbase = V + (size_t)bh * SEQ * HDIM;

    const int lrow0 = tid >> 4;             // 0..15
    const int ld0   = (tid & 15) * 4;       // 0..60

    // Load Q tile transposed with 1/sqrt(D) folded in
    const float qscale = 0.125f;
#pragma unroll
    for (int rr = lrow0; rr < 128; rr += 16) {
        float4 q4 = *(const float4*)(Qbase + (size_t)rr * HDIM + ld0);
        Qs[(ld0 + 0) * QK_ST + rr] = q4.x * qscale;
        Qs[(ld0 + 1) * QK_ST + rr] = q4.y * qscale;
        Qs[(ld0 + 2) * QK_ST + rr] = q4.z * qscale;
        Qs[(ld0 + 3) * QK_ST + rr] = q4.w * qscale;
    }

    float m_r[8], l_r[8], o[8][4];
#pragma unroll
    for (int i = 0; i < 8; i++) {
        m_r[i] = -1e30f; l_r[i] = 0.f;
        o[i][0] = o[i][1] = o[i][2] = o[i][3] = 0.f;
    }

    for (int it = 0; it < SEQ / 128; ++it) {
        const float* Kb = Kbase + (size_t)it * 128 * HDIM;
        const float* Vb = Vbase + (size_t)it * 128 * HDIM;

        __syncthreads();   // previous iter's smem reads complete
#pragma unroll
        for (int rr = lrow0; rr < 128; rr += 16) {
            float4 k4 = *(const float4*)(Kb + (size_t)rr * HDIM + ld0);
            Ks[(ld0 + 0) * QK_ST + rr] = k4.x;
            Ks[(ld0 + 1) * QK_ST + rr] = k4.y;
            Ks[(ld0 + 2) * QK_ST + rr] = k4.z;
            Ks[(ld0 + 3) * QK_ST + rr] = k4.w;
            float4 v4 = *(const float4*)(Vb + (size_t)rr * HDIM + ld0);
            *(float4*)&Vs[rr * V_ST + ld0] = v4;
        }
        __syncthreads();

        // S = Q * K^T  (128x128, k over 64 dims)
        float sc[8][8];
#pragma unroll
        for (int i = 0; i < 8; i++)
#pragma unroll
            for (int j = 0; j < 8; j++) sc[i][j] = 0.f;

#pragma unroll 8
        for (int k = 0; k < 64; k++) {
            float a[8], bb[8];
            *(float4*)&a[0]  = *(const float4*)&Qs[k * QK_ST + ty * 4];
            *(float4*)&a[4]  = *(const float4*)&Qs[k * QK_ST + ty * 4 + 64];
            *(float4*)&bb[0] = *(const float4*)&Ks[k * QK_ST + tx * 4];
            *(float4*)&bb[4] = *(const float4*)&Ks[k * QK_ST + tx * 4 + 64];
#pragma unroll
            for (int i = 0; i < 8; i++)
#pragma unroll
                for (int j = 0; j < 8; j++)
                    sc[i][j] += a[i] * bb[j];
        }

        // Online softmax per row (rows shared across the 16 tx lanes)
#pragma unroll
        for (int i = 0; i < 8; i++) {
            float mx = sc[i][0];
#pragma unroll
            for (int j = 1; j < 8; j++) mx = fmaxf(mx, sc[i][j]);
            mx = fmaxf(mx, __shfl_xor_sync(0xffffffffu, mx, 1));
            mx = fmaxf(mx, __shfl_xor_sync(0xffffffffu, mx, 2));
            mx = fmaxf(mx, __shfl_xor_sync(0xffffffffu, mx, 4));
            mx = fmaxf(mx, __shfl_xor_sync(0xffffffffu, mx, 8));
            float mnew = fmaxf(m_r[i], mx);
            float corr = __expf(m_r[i] - mnew);
            m_r[i] = mnew;
            float rs = 0.f;
#pragma unroll
            for (int j = 0; j < 8; j++) {
                float p = __expf(sc[i][j] - mnew);
                sc[i][j] = p;
                rs += p;
            }
            rs += __shfl_xor_sync(0xffffffffu, rs, 1);
            rs += __shfl_xor_sync(0xffffffffu, rs, 2);
            rs += __shfl_xor_sync(0xffffffffu, rs, 4);
            rs += __shfl_xor_sync(0xffffffffu, rs, 8);
            l_r[i] = l_r[i] * corr + rs;
            o[i][0] *= corr; o[i][1] *= corr; o[i][2] *= corr; o[i][3] *= corr;
        }

        // Stage P transposed [c][r]
#pragma unroll
        for (int i = 0; i < 8; i++) {
            int r = ty * 4 + i + ((i >= 4) ? 60 : 0);
#pragma unroll
            for (int j = 0; j < 8; j++) {
                int c = tx * 4 + j + ((j >= 4) ? 60 : 0);
                Ps[c * P_ST + r] = sc[i][j];
            }
        }
        __syncthreads();

        // O += P * V   (o cols = d = tx*4..tx*4+3)
#pragma unroll 4
        for (int c = 0; c < 128; c++) {
            float4 vv = *(const float4*)&Vs[c * V_ST + tx * 4];
#pragma unroll
            for (int i = 0; i < 8; i++) {
                int r = ty * 4 + i + ((i >= 4) ? 60 : 0);
                float p = Ps[c * P_ST + r];
                o[i][0] += p * vv.x;
                o[i][1] += p * vv.y;
                o[i][2] += p * vv.z;
                o[i][3] += p * vv.w;
            }
        }
    }

    // Epilogue: normalize, write [B,S,C]
#pragma unroll
    for (int i = 0; i < 8; i++) {
        int r = ty * 4 + i + ((i >= 4) ? 60 : 0);
        float inv = 1.f / l_r[i];
        float4 ov;
        ov.x = o[i][0] * inv; ov.y = o[i][1] * inv;
        ov.z = o[i][2] * inv; ov.w = o[i][3] * inv;
        int srow = qt * 128 + r;
        *(float4*)&Out[((size_t)(b * SEQ + srow)) * CDIM + h * HDIM + tx * 4] = ov;
    }
}

// ---------------------------------------------------------------------------
// Launch
// ---------------------------------------------------------------------------
extern "C" void kernel_launch(void* const* d_in, const int* in_sizes, int n_in,
                              void* d_out, int out_size)
{
    const float* hidden = (const float*)d_in[0];
    const float* cosb   = (const float*)d_in[1];
    const float* sinb   = (const float*)d_in[2];
    const float* qkv_w  = (const float*)d_in[3];
    const float* qkv_b  = (const float*)d_in[4];
    const float* proj_w = (const float*)d_in[5];
    const float* proj_b = (const float*)d_in[6];
    float* out = (float*)d_out;

    float *p_qkv, *p_q, *p_k, *p_v, *p_attn;
    cudaGetSymbolAddress((void**)&p_qkv,  g_qkv);
    cudaGetSymbolAddress((void**)&p_q,    g_q);
    cudaGetSymbolAddress((void**)&p_k,    g_k);
    cudaGetSymbolAddress((void**)&p_v,    g_v);
    cudaGetSymbolAddress((void**)&p_attn, g_attn);

    static bool attr_set = false;
    if (!attr_set) {
        cudaFuncSetAttribute(attn_kernel,
                             cudaFuncAttributeMaxDynamicSharedMemorySize,
                             ATTN_SMEM_BYTES);
        attr_set = true;
    }

    // 1) QKV GEMM: [8192,1024] x [3072,1024]^T -> [8192,3072]
    sgemm_nt_bias<<<dim3(N3 / 128, MTOT / 128), 256>>>(
        hidden, qkv_w, qkv_b, p_qkv, MTOT, N3, CDIM);

    // 2) RoPE + split to head-major
    rope_split_kernel<<<(MTOT * CDIM) / 256, 256>>>(
        p_qkv, cosb, sinb, p_q, p_k, p_v);

    // 3) Attention (flash, fp32)
    attn_kernel<<<dim3(SEQ / 128, BATCH * NHEADS), 256, ATTN_SMEM_BYTES>>>(
        p_q, p_k, p_v, p_attn);

    // 4) Projection GEMM: [8192,1024] x [1024,1024]^T -> [8192,1024]
    sgemm_nt_bias<<<dim3(CDIM / 128, MTOT / 128), 256>>>(
        p_attn, proj_w, proj_b, out, MTOT, CDIM, CDIM);
}

// round 2
// speedup vs baseline: 1.1730x; 1.1730x over previous
#include <cuda_runtime.h>
#include <cuda_fp16.h>

// Problem constants
#define NHEADS 16
#define HDIM   64
#define BATCH  4
#define SEQ    2048
#define CDIM   1024
#define MTOT   (BATCH * SEQ)          // 8192
#define N3     (3 * CDIM)             // 3072

// Scratch
__device__ float g_qkv[(size_t)MTOT * N3];                    // 96 MB
__device__ float g_q[(size_t)BATCH * NHEADS * SEQ * HDIM];    // 32 MB
__device__ float g_k[(size_t)BATCH * NHEADS * SEQ * HDIM];    // 32 MB
__device__ float g_v[(size_t)BATCH * NHEADS * SEQ * HDIM];    // 32 MB
__device__ float g_attn[(size_t)MTOT * CDIM];                 // 32 MB

// ---------------------------------------------------------------------------
// split-fp16 helpers (Markidis emulation: x = hi + lo, fp32-quality accum)
// ---------------------------------------------------------------------------
__device__ __forceinline__ void splitf(float x, float y, unsigned &h, unsigned &l) {
    __half hx = __float2half_rn(x), hy = __float2half_rn(y);
    __half lx = __float2half_rn(x - __half2float(hx));
    __half ly = __float2half_rn(y - __half2float(hy));
    h = (unsigned)__half_as_ushort(hx) | ((unsigned)__half_as_ushort(hy) << 16);
    l = (unsigned)__half_as_ushort(lx) | ((unsigned)__half_as_ushort(ly) << 16);
}

__device__ __forceinline__ void mma16(float c[4], const unsigned a[4],
                                      unsigned b0, unsigned b1) {
    asm volatile(
        "mma.sync.aligned.m16n8k16.row.col.f32.f16.f16.f32 "
        "{%0,%1,%2,%3}, {%4,%5,%6,%7}, {%8,%9}, {%0,%1,%2,%3};"
        : "+f"(c[0]), "+f"(c[1]), "+f"(c[2]), "+f"(c[3])
        : "r"(a[0]), "r"(a[1]), "r"(a[2]), "r"(a[3]), "r"(b0), "r"(b1));
}

// ---------------------------------------------------------------------------
// GEMM (NT) via split-fp16 tensor cores.
// C[m,n] = sum_k A[m,k]*W[n,k] + bias[n].  128x128 tile, BK=32, 8 warps (2x4),
// warp tile 64x32. Smem stores half2 words [row][k2], stride 20 (conflict-free
// fragment loads: stride%8==4 -> banks 4g+qd distinct).
// ---------------------------------------------------------------------------
#define AST 20

__global__ __launch_bounds__(256) void hgemm_nt_bias(
    const float* __restrict__ A, const float* __restrict__ W,
    const float* __restrict__ bias, float* __restrict__ C,
    int M, int N, int K)
{
    __shared__ unsigned Ash[128][AST];
    __shared__ unsigned Asl[128][AST];
    __shared__ unsigned Bsh[128][AST];
    __shared__ unsigned Bsl[128][AST];

    const int tid  = threadIdx.x;
    const int warp = tid >> 5, lane = tid & 31;
    const int g = lane >> 2, qd = lane & 3;
    const int wm = (warp >> 2) * 64;      // 0 or 64
    const int wn = (warp & 3) * 32;       // 0..96
    const int bm = blockIdx.y * 128;
    const int bn = blockIdx.x * 128;

    float acc[4][4][4];
#pragma unroll
    for (int mt = 0; mt < 4; mt++)
#pragma unroll
        for (int nt = 0; nt < 4; nt++)
#pragma unroll
            for (int i = 0; i < 4; i++) acc[mt][nt][i] = 0.f;

    // gmem load mapping: 1024 float4 per operand tile, 4 per thread
    const int lr = tid >> 1;              // row for pair-of-float4 scheme
    // use idx scheme: idx = tid + i*256 ; row = idx>>3 ; kc = (idx&7)*4
    float4 aReg[4], bReg[4];
#pragma unroll
    for (int i = 0; i < 4; i++) {
        int idx = tid + i * 256;
        int r = idx >> 3, kc = (idx & 7) * 4;
        aReg[i] = *(const float4*)(A + (size_t)(bm + r) * K + kc);
        bReg[i] = *(const float4*)(W + (size_t)(bn + r) * K + kc);
    }
    (void)lr;

    for (int kt = 0; kt < K; kt += 32) {
        __syncthreads();
#pragma unroll
        for (int i = 0; i < 4; i++) {
            int idx = tid + i * 256;
            int r = idx >> 3, kc = (idx & 7) * 4;
            unsigned h0, l0, h1, l1;
            splitf(aReg[i].x, aReg[i].y, h0, l0);
            splitf(aReg[i].z, aReg[i].w, h1, l1);
            Ash[r][kc / 2] = h0; Ash[r][kc / 2 + 1] = h1;
            Asl[r][kc / 2] = l0; Asl[r][kc / 2 + 1] = l1;
            splitf(bReg[i].x, bReg[i].y, h0, l0);
            splitf(bReg[i].z, bReg[i].w, h1, l1);
            Bsh[r][kc / 2] = h0; Bsh[r][kc / 2 + 1] = h1;
            Bsl[r][kc / 2] = l0; Bsl[r][kc / 2 + 1] = l1;
        }
        __syncthreads();
        if (kt + 32 < K) {
#pragma unroll
            for (int i = 0; i < 4; i++) {
                int idx = tid + i * 256;
                int r = idx >> 3, kc = (idx & 7) * 4;
                aReg[i] = *(const float4*)(A + (size_t)(bm + r) * K + kt + 32 + kc);
                bReg[i] = *(const float4*)(W + (size_t)(bn + r) * K + kt + 32 + kc);
            }
        }

#pragma unroll
        for (int ks = 0; ks < 2; ks++) {
            unsigned ah[4][4], al[4][4];
#pragma unroll
            for (int mt = 0; mt < 4; mt++) {
                int r = wm + mt * 16 + g;
                ah[mt][0] = Ash[r][ks * 8 + qd];
                ah[mt][1] = Ash[r + 8][ks * 8 + qd];
                ah[mt][2] = Ash[r][ks * 8 + 4 + qd];
                ah[mt][3] = Ash[r + 8][ks * 8 + 4 + qd];
                al[mt][0] = Asl[r][ks * 8 + qd];
                al[mt][1] = Asl[r + 8][ks * 8 + qd];
                al[mt][2] = Asl[r][ks * 8 + 4 + qd];
                al[mt][3] = Asl[r + 8][ks * 8 + 4 + qd];
            }
#pragma unroll
            for (int nt = 0; nt < 4; nt++) {
                int c = wn + nt * 8 + g;
                unsigned bh0 = Bsh[c][ks * 8 + qd];
                unsigned bh1 = Bsh[c][ks * 8 + 4 + qd];
                unsigned bl0 = Bsl[c][ks * 8 + qd];
                unsigned bl1 = Bsl[c][ks * 8 + 4 + qd];
#pragma unroll
                for (int mt = 0; mt < 4; mt++) {
                    mma16(acc[mt][nt], ah[mt], bh0, bh1);
                    mma16(acc[mt][nt], ah[mt], bl0, bl1);
                    mma16(acc[mt][nt], al[mt], bh0, bh1);
                }
            }
        }
    }

    // epilogue
#pragma unroll
    for (int mt = 0; mt < 4; mt++) {
        int r0 = bm + wm + mt * 16 + g;
#pragma unroll
        for (int nt = 0; nt < 4; nt++) {
            int cn = bn + wn + nt * 8 + 2 * qd;
            float b0 = bias[cn], b1 = bias[cn + 1];
            float2 v0 = make_float2(acc[mt][nt][0] + b0, acc[mt][nt][1] + b1);
            float2 v1 = make_float2(acc[mt][nt][2] + b0, acc[mt][nt][3] + b1);
            *(float2*)&C[(size_t)r0 * N + cn]       = v0;
            *(float2*)&C[(size_t)(r0 + 8) * N + cn] = v1;
        }
    }
}

// ---------------------------------------------------------------------------
// RoPE + split qkv into head-major q/k/v [b,h,s,d]
// ---------------------------------------------------------------------------
__global__ __launch_bounds__(256) void rope_split_kernel(
    const float* __restrict__ qkv, const float* __restrict__ cosb,
    const float* __restrict__ sinb, float* __restrict__ q,
    float* __restrict__ k, float* __restrict__ v)
{
    int idx = blockIdx.x * 256 + threadIdx.x;
    if (idx >= MTOT * CDIM) return;
    int m  = idx >> 10;
    int hd = idx & 1023;
    int b  = m >> 11;
    int s  = m & 2047;
    int h  = hd >> 6;
    int d  = hd & 63;

    const float* row = qkv + (size_t)m * N3;
    float cs = cosb[(size_t)m * HDIM + d];
    float sn = sinb[(size_t)m * HDIM + d];
    size_t oidx = (((size_t)(b * NHEADS + h) * SEQ) + s) * HDIM + d;

    float xq = row[hd];
    float rq = (d < 32) ? -row[hd + 32] : row[hd - 32];
    q[oidx] = xq * cs + rq * sn;

    float xk = row[CDIM + hd];
    float rk = (d < 32) ? -row[CDIM + hd + 32] : row[CDIM + hd - 32];
    k[oidx] = xk * cs + rk * sn;

    v[oidx] = row[2 * CDIM + hd];
}

// ---------------------------------------------------------------------------
// Flash attention via split-fp16 mma. Block = 128 q rows, 8 warps, each warp
// owns 16 q rows (warp-local softmax). KV tile = 64.
// Q: [q][d2] stride 36 ; K: [kv][d2] stride 36 ; V transposed: [d][kv2] str 36.
// P stays in registers (QK C-frag == PV A-frag layout).
// ---------------------------------------------------------------------------
#define KVT 64
#define QS  36
#define KS2 36
#define VS2 36
#define ATTN_SMEM_WORDS (128*QS*2 + KVT*KS2*2 + HDIM*VS2*2)
#define ATTN_SMEM_BYTES (ATTN_SMEM_WORDS * 4)   // 73728

__global__ __launch_bounds__(256) void attn_mma_kernel(
    const float* __restrict__ Q, const float* __restrict__ K,
    const float* __restrict__ V, float* __restrict__ Out)
{
    extern __shared__ unsigned sm[];
    unsigned* Qh = sm;
    unsigned* Ql = Qh + 128 * QS;
    unsigned* Kh = Ql + 128 * QS;
    unsigned* Kl = Kh + KVT * KS2;
    unsigned* Vh = Kl + KVT * KS2;
    unsigned* Vl = Vh + HDIM * VS2;

    const int tid  = threadIdx.x;
    const int warp = tid >> 5, lane = tid & 31;
    const int g = lane >> 2, qd = lane & 3;
    const int qt = blockIdx.x;
    const int bh = blockIdx.y;
    const int b  = bh >> 4, h = bh & 15;

    const float* Qbase = Q + ((size_t)bh * SEQ + (size_t)qt * 128) * HDIM;
    const float* Kbase = K + (size_t)bh * SEQ * HDIM;
    const float* Vbase = V + (size_t)bh * SEQ * HDIM;

    // Load Q once (scale 1/sqrt(64) folded in)
#pragma unroll
    for (int i = 0; i < 8; i++) {
        int idx = tid + i * 256;         // 2048 float4
        int r = idx >> 4, d = (idx & 15) * 4;
        float4 q4 = *(const float4*)(Qbase + (size_t)r * HDIM + d);
        unsigned h0, l0, h1, l1;
        splitf(q4.x * 0.125f, q4.y * 0.125f, h0, l0);
        splitf(q4.z * 0.125f, q4.w * 0.125f, h1, l1);
        Qh[r * QS + d / 2] = h0; Qh[r * QS + d / 2 + 1] = h1;
        Ql[r * QS + d / 2] = l0; Ql[r * QS + d / 2 + 1] = l1;
    }

    float m0 = -1e30f, m1 = -1e30f, lsum0 = 0.f, lsum1 = 0.f;
    float o[8][4];
#pragma unroll
    for (int nt = 0; nt < 8; nt++)
#pragma unroll
        for (int i = 0; i < 4; i++) o[nt][i] = 0.f;

    const int q0 = warp * 16;
    __half* VhH = (__half*)Vh;
    __half* VlH = (__half*)Vl;

    for (int t = 0; t < SEQ / KVT; t++) {
        __syncthreads();
        // Stage K (natural) and V (transposed) tiles, split hi/lo
#pragma unroll
        for (int i = 0; i < 4; i++) {
            int idx = tid + i * 256;     // 1024 float4 over 64x64
            int r = idx >> 4, d = (idx & 15) * 4;
            const float* kp = Kbase + ((size_t)t * KVT + r) * HDIM + d;
            float4 k4 = *(const float4*)kp;
            unsigned h0, l0, h1, l1;
            splitf(k4.x, k4.y, h0, l0);
            splitf(k4.z, k4.w, h1, l1);
            Kh[r * KS2 + d / 2] = h0; Kh[r * KS2 + d / 2 + 1] = h1;
            Kl[r * KS2 + d / 2] = l0; Kl[r * KS2 + d / 2 + 1] = l1;

            const float* vp = Vbase + ((size_t)t * KVT + r) * HDIM + d;
            float4 v4 = *(const float4*)vp;
#pragma unroll
            for (int j = 0; j < 4; j++) {
                float x = (j == 0) ? v4.x : (j == 1) ? v4.y : (j == 2) ? v4.z : v4.w;
                __half hx = __float2half_rn(x);
                __half lx = __float2half_rn(x - __half2float(hx));
                VhH[(d + j) * (VS2 * 2) + r] = hx;
                VlH[(d + j) * (VS2 * 2) + r] = lx;
            }
        }
        __syncthreads();

        // ---- S = Q K^T  (16q x 64kv per warp) ----
        float sc[8][4];
#pragma unroll
        for (int nt = 0; nt < 8; nt++)
#pragma unroll
            for (int i = 0; i < 4; i++) sc[nt][i] = 0.f;

#pragma unroll
        for (int ks = 0; ks < 4; ks++) {
            unsigned ah[4], al[4];
            int r = q0 + g;
            ah[0] = Qh[r * QS + ks * 8 + qd];
            ah[1] = Qh[(r + 8) * QS + ks * 8 + qd];
            ah[2] = Qh[r * QS + ks * 8 + 4 + qd];
            ah[3] = Qh[(r + 8) * QS + ks * 8 + 4 + qd];
            al[0] = Ql[r * QS + ks * 8 + qd];
            al[1] = Ql[(r + 8) * QS + ks * 8 + qd];
            al[2] = Ql[r * QS + ks * 8 + 4 + qd];
            al[3] = Ql[(r + 8) * QS + ks * 8 + 4 + qd];
#pragma unroll
            for (int nt = 0; nt < 8; nt++) {
                int c = nt * 8 + g;
                unsigned bh0 = Kh[c * KS2 + ks * 8 + qd];
                unsigned bh1 = Kh[c * KS2 + ks * 8 + 4 + qd];
                unsigned bl0 = Kl[c * KS2 + ks * 8 + qd];
                unsigned bl1 = Kl[c * KS2 + ks * 8 + 4 + qd];
                mma16(sc[nt], ah, bh0, bh1);
                mma16(sc[nt], ah, bl0, bl1);
                mma16(sc[nt], al, bh0, bh1);
            }
        }

        // ---- online softmax (rows g and g+8, warp-local over quads) ----
        float mx0 = -1e30f, mx1 = -1e30f;
#pragma unroll
        for (int nt = 0; nt < 8; nt++) {
            mx0 = fmaxf(mx0, fmaxf(sc[nt][0], sc[nt][1]));
            mx1 = fmaxf(mx1, fmaxf(sc[nt][2], sc[nt][3]));
        }
        mx0 = fmaxf(mx0, __shfl_xor_sync(0xffffffffu, mx0, 1));
        mx0 = fmaxf(mx0, __shfl_xor_sync(0xffffffffu, mx0, 2));
        mx1 = fmaxf(mx1, __shfl_xor_sync(0xffffffffu, mx1, 1));
        mx1 = fmaxf(mx1, __shfl_xor_sync(0xffffffffu, mx1, 2));
        float nm0 = fmaxf(m0, mx0), nm1 = fmaxf(m1, mx1);
        float cr0 = __expf(m0 - nm0), cr1 = __expf(m1 - nm1);
        m0 = nm0; m1 = nm1;
        float rs0 = 0.f, rs1 = 0.f;
#pragma unroll
        for (int nt = 0; nt < 8; nt++) {
            sc[nt][0] = __expf(sc[nt][0] - nm0); rs0 += sc[nt][0];
            sc[nt][1] = __expf(sc[nt][1] - nm0); rs0 += sc[nt][1];
            sc[nt][2] = __expf(sc[nt][2] - nm1); rs1 += sc[nt][2];
            sc[nt][3] = __expf(sc[nt][3] - nm1); rs1 += sc[nt][3];
        }
        rs0 += __shfl_xor_sync(0xffffffffu, rs0, 1);
        rs0 += __shfl_xor_sync(0xffffffffu, rs0, 2);
        rs1 += __shfl_xor_sync(0xffffffffu, rs1, 1);
        rs1 += __shfl_xor_sync(0xffffffffu, rs1, 2);
        lsum0 = lsum0 * cr0 + rs0;
        lsum1 = lsum1 * cr1 + rs1;
#pragma unroll
        for (int nt = 0; nt < 8; nt++) {
            o[nt][0] *= cr0; o[nt][1] *= cr0;
            o[nt][2] *= cr1; o[nt][3] *= cr1;
        }

        // ---- O += P V   (P from registers: C-frag == A-frag layout) ----
#pragma unroll
        for (int j = 0; j < 4; j++) {        // kv k16 steps
            unsigned ph[4], pl[4];
            splitf(sc[2 * j][0],     sc[2 * j][1],     ph[0], pl[0]);
            splitf(sc[2 * j][2],     sc[2 * j][3],     ph[1], pl[1]);
            splitf(sc[2 * j + 1][0], sc[2 * j + 1][1], ph[2], pl[2]);
            splitf(sc[2 * j + 1][2], sc[2 * j + 1][3], ph[3], pl[3]);
#pragma unroll
            for (int nt = 0; nt < 8; nt++) { // d tiles
                int c = nt * 8 + g;
                unsigned bh0 = Vh[c * VS2 + j * 8 + qd];
                unsigned bh1 = Vh[c * VS2 + j * 8 + 4 + qd];
                unsigned bl0 = Vl[c * VS2 + j * 8 + qd];
                unsigned bl1 = Vl[c * VS2 + j * 8 + 4 + qd];
                mma16(o[nt], ph, bh0, bh1);
                mma16(o[nt], ph, bl0, bl1);
                mma16(o[nt], pl, bh0, bh1);
            }
        }
    }

    // ---- epilogue: normalize, write to [B,S,C] layout ----
    float inv0 = 1.f / lsum0, inv1 = 1.f / lsum1;
    int row0 = qt * 128 + q0 + g;
#pragma unroll
    for (int nt = 0; nt < 8; nt++) {
        int col = h * HDIM + nt * 8 + 2 * qd;
        float2 v0 = make_float2(o[nt][0] * inv0, o[nt][1] * inv0);
        float2 v1 = make_float2(o[nt][2] * inv1, o[nt][3] * inv1);
        *(float2*)&Out[((size_t)(b * SEQ + row0)) * CDIM + col]     = v0;
        *(float2*)&Out[((size_t)(b * SEQ + row0 + 8)) * CDIM + col] = v1;
    }
}

// ---------------------------------------------------------------------------
// Launch
// ---------------------------------------------------------------------------
extern "C" void kernel_launch(void* const* d_in, const int* in_sizes, int n_in,
                              void* d_out, int out_size)
{
    const float* hidden = (const float*)d_in[0];
    const float* cosb   = (const float*)d_in[1];
    const float* sinb   = (const float*)d_in[2];
    const float* qkv_w  = (const float*)d_in[3];
    const float* qkv_b  = (const float*)d_in[4];
    const float* proj_w = (const float*)d_in[5];
    const float* proj_b = (const float*)d_in[6];
    float* out = (float*)d_out;

    float *p_qkv, *p_q, *p_k, *p_v, *p_attn;
    cudaGetSymbolAddress((void**)&p_qkv,  g_qkv);
    cudaGetSymbolAddress((void**)&p_q,    g_q);
    cudaGetSymbolAddress((void**)&p_k,    g_k);
    cudaGetSymbolAddress((void**)&p_v,    g_v);
    cudaGetSymbolAddress((void**)&p_attn, g_attn);

    static bool attr_set = false;
    if (!attr_set) {
        cudaFuncSetAttribute(attn_mma_kernel,
                             cudaFuncAttributeMaxDynamicSharedMemorySize,
                             ATTN_SMEM_BYTES);
        attr_set = true;
    }

    // 1) QKV GEMM
    hgemm_nt_bias<<<dim3(N3 / 128, MTOT / 128), 256>>>(
        hidden, qkv_w, qkv_b, p_qkv, MTOT, N3, CDIM);

    // 2) RoPE + split
    rope_split_kernel<<<(MTOT * CDIM) / 256, 256>>>(
        p_qkv, cosb, sinb, p_q, p_k, p_v);

    // 3) Attention (flash, split-fp16 mma)
    attn_mma_kernel<<<dim3(SEQ / 128, BATCH * NHEADS), 256, ATTN_SMEM_BYTES>>>(
        p_q, p_k, p_v, p_attn);

    // 4) Projection GEMM
    hgemm_nt_bias<<<dim3(CDIM / 128, MTOT / 128), 256>>>(
        p_attn, proj_w, proj_b, out, MTOT, CDIM, CDIM);
}

// round 4
// speedup vs baseline: 2.4403x; 2.0805x over previous
#include <cuda_runtime.h>
#include <cuda_fp16.h>

// Problem constants
#define NHEADS 16
#define HDIM   64
#define BATCH  4
#define SEQ    2048
#define CDIM   1024
#define MTOT   (BATCH * SEQ)          // 8192
#define N3     (3 * CDIM)             // 3072

// ---------------------------------------------------------------------------
// Scratch (__device__ globals; allocation-free rule)
// ---------------------------------------------------------------------------
__device__ float  g_qkv[(size_t)MTOT * N3];                       // 96 MB
__device__ __half g_hid_h[(size_t)MTOT * CDIM];                   // 16 MB
__device__ __half g_hid_l[(size_t)MTOT * CDIM];
__device__ __half g_qkvw_h[(size_t)N3 * CDIM];                    // 6 MB
__device__ __half g_qkvw_l[(size_t)N3 * CDIM];
__device__ __half g_projw_h[(size_t)CDIM * CDIM];                 // 2 MB
__device__ __half g_projw_l[(size_t)CDIM * CDIM];
__device__ __half g_qh[(size_t)MTOT * CDIM];                      // 16 MB each
__device__ __half g_ql[(size_t)MTOT * CDIM];
__device__ __half g_kh[(size_t)MTOT * CDIM];
__device__ __half g_kl[(size_t)MTOT * CDIM];
__device__ __half g_vh[(size_t)MTOT * CDIM];
__device__ __half g_vl[(size_t)MTOT * CDIM];
__device__ __half g_attn_h[(size_t)MTOT * CDIM];
__device__ __half g_attn_l[(size_t)MTOT * CDIM];

// ---------------------------------------------------------------------------
// PTX helpers
// ---------------------------------------------------------------------------
__device__ __forceinline__ unsigned smem_u32(const void* p) {
    return (unsigned)__cvta_generic_to_shared(p);
}
__device__ __forceinline__ void cp16(unsigned d, const void* s) {
    asm volatile("cp.async.cg.shared.global [%0], [%1], 16;" :: "r"(d), "l"(s));
}
#define CP_COMMIT() asm volatile("cp.async.commit_group;" ::: "memory")
#define CP_WAIT1()  asm volatile("cp.async.wait_group 1;" ::: "memory")

__device__ __forceinline__ void ldsm4(unsigned r[4], unsigned a) {
    asm volatile("ldmatrix.sync.aligned.m8n8.x4.shared.b16 {%0,%1,%2,%3}, [%4];"
        : "=r"(r[0]), "=r"(r[1]), "=r"(r[2]), "=r"(r[3]) : "r"(a));
}
__device__ __forceinline__ void ldsm4t(unsigned r[4], unsigned a) {
    asm volatile("ldmatrix.sync.aligned.m8n8.x4.trans.shared.b16 {%0,%1,%2,%3}, [%4];"
        : "=r"(r[0]), "=r"(r[1]), "=r"(r[2]), "=r"(r[3]) : "r"(a));
}
__device__ __forceinline__ void splitf(float x, float y, unsigned &h, unsigned &l) {
    __half hx = __float2half_rn(x), hy = __float2half_rn(y);
    __half lx = __float2half_rn(x - __half2float(hx));
    __half ly = __float2half_rn(y - __half2float(hy));
    h = (unsigned)__half_as_ushort(hx) | ((unsigned)__half_as_ushort(hy) << 16);
    l = (unsigned)__half_as_ushort(lx) | ((unsigned)__half_as_ushort(ly) << 16);
}
__device__ __forceinline__ void mma16(float c[4], const unsigned a[4],
                                      unsigned b0, unsigned b1) {
    asm volatile(
        "mma.sync.aligned.m16n8k16.row.col.f32.f16.f16.f32 "
        "{%0,%1,%2,%3}, {%4,%5,%6,%7}, {%8,%9}, {%0,%1,%2,%3};"
        : "+f"(c[0]), "+f"(c[1]), "+f"(c[2]), "+f"(c[3])
        : "r"(a[0]), "r"(a[1]), "r"(a[2]), "r"(a[3]), "r"(b0), "r"(b1));
}

// ---------------------------------------------------------------------------
// Split fp32 -> (hi, lo) fp16 arrays.  n4 = element count / 4.
// ---------------------------------------------------------------------------
__global__ __launch_bounds__(256) void split_kernel(
    const float* __restrict__ in, __half* __restrict__ oh,
    __half* __restrict__ ol, int n4)
{
    int idx = blockIdx.x * 256 + threadIdx.x;
    if (idx >= n4) return;
    float4 x = ((const float4*)in)[idx];
    unsigned h0, l0, h1, l1;
    splitf(x.x, x.y, h0, l0);
    splitf(x.z, x.w, h1, l1);
    ((unsigned*)oh)[idx * 2]     = h0;
    ((unsigned*)oh)[idx * 2 + 1] = h1;
    ((unsigned*)ol)[idx * 2]     = l0;
    ((unsigned*)ol)[idx * 2 + 1] = l1;
}

// ---------------------------------------------------------------------------
// GEMM (NT), split-fp16 tensor cores, cp.async double-buffered, ldmatrix.
// C[m,n] = sum_k A[m,k]*W[n,k] + bias[n].
// Tile 128x128, BK=32, 8 warps (2x4), warp tile 64x32.
// Smem per stage (halves): Ah 0, Al 4096, Bh 8192, Bl 12288 (each 128x32,
// 64B rows, XOR swizzle: physSeg = seg ^ ((row>>1)&3)).
// ---------------------------------------------------------------------------
#define G_STAGE 16384   // halves per stage
#define G_SMEM_BYTES (2 * G_STAGE * 2)   // 64 KB

__device__ __forceinline__ void gemm_stage_load(
    __half* sb, const __half* Ah, const __half* Al,
    const __half* Bh, const __half* Bl,
    int bm, int bn, int kt, int K, int tid)
{
#pragma unroll
    for (int i = 0; i < 2; i++) {
        int idx = tid + i * 256;
        int r = idx >> 2, s = idx & 3;
        unsigned off = r * 32 + ((s ^ ((r >> 1) & 3)) * 8);
        unsigned d = smem_u32(sb + off);
        size_t ga = (size_t)(bm + r) * K + kt + s * 8;
        size_t gb = (size_t)(bn + r) * K + kt + s * 8;
        cp16(d,             Ah + ga);
        cp16(d + 4096 * 2,  Al + ga);
        cp16(d + 8192 * 2,  Bh + gb);
        cp16(d + 12288 * 2, Bl + gb);
    }
}

__global__ __launch_bounds__(256, 2) void hgemm_nt_bias(
    const __half* __restrict__ Ah, const __half* __restrict__ Al,
    const __half* __restrict__ Bh, const __half* __restrict__ Bl,
    const float* __restrict__ bias, float* __restrict__ C,
    int M, int N, int K)
{
    extern __shared__ __half sm[];
    const int tid  = threadIdx.x;
    const int warp = tid >> 5, lane = tid & 31;
    const int g = lane >> 2, qd = lane & 3;
    const int ln15 = lane & 15, lhi = lane >> 4;
    const int wm = (warp >> 2) * 64;
    const int wn = (warp & 3) * 32;
    const int bm = blockIdx.y * 128;
    const int bn = blockIdx.x * 128;

    float acc[4][4][4];
#pragma unroll
    for (int mt = 0; mt < 4; mt++)
#pragma unroll
        for (int nt = 0; nt < 4; nt++)
#pragma unroll
            for (int i = 0; i < 4; i++) acc[mt][nt][i] = 0.f;

    // prologue: stages 0, 1
    gemm_stage_load(sm, Ah, Al, Bh, Bl, bm, bn, 0, K, tid);
    CP_COMMIT();
    gemm_stage_load(sm + G_STAGE, Ah, Al, Bh, Bl, bm, bn, 32, K, tid);
    CP_COMMIT();

    int st = 0;
    for (int kt = 0; kt < K; kt += 32, st ^= 1) {
        CP_WAIT1();
        __syncthreads();
        unsigned baseu = smem_u32(sm + st * G_STAGE);

#pragma unroll
        for (int ks = 0; ks < 2; ks++) {
            unsigned bhf[8], blf[8];
#pragma unroll
            for (int blk = 0; blk < 2; blk++) {
                int r = wn + blk * 16 + ln15;
                int s = 2 * ks + lhi;
                unsigned off = r * 32 + ((s ^ ((r >> 1) & 3)) * 8);
                ldsm4(&bhf[blk * 4], baseu + (8192 + off) * 2);
                ldsm4(&blf[blk * 4], baseu + (12288 + off) * 2);
            }
#pragma unroll
            for (int mt = 0; mt < 4; mt++) {
                int r = wm + mt * 16 + ln15;
                int s = 2 * ks + lhi;
                unsigned off = r * 32 + ((s ^ ((r >> 1) & 3)) * 8);
                unsigned ah[4], al[4];
                ldsm4(ah, baseu + off * 2);
                ldsm4(al, baseu + (4096 + off) * 2);
#pragma unroll
                for (int blk = 0; blk < 2; blk++)
#pragma unroll
                    for (int e = 0; e < 2; e++) {
                        int nt = blk * 2 + e;
                        unsigned b0h = bhf[blk * 4 + e], b1h = bhf[blk * 4 + 2 + e];
                        unsigned b0l = blf[blk * 4 + e], b1l = blf[blk * 4 + 2 + e];
                        mma16(acc[mt][nt], ah, b0h, b1h);
                        mma16(acc[mt][nt], ah, b0l, b1l);
                        mma16(acc[mt][nt], al, b0h, b1h);
                    }
            }
        }
        __syncthreads();
        if (kt + 64 < K)
            gemm_stage_load(sm + st * G_STAGE, Ah, Al, Bh, Bl, bm, bn, kt + 64, K, tid);
        CP_COMMIT();
    }

    // epilogue
#pragma unroll
    for (int mt = 0; mt < 4; mt++) {
        int r0 = bm + wm + mt * 16 + g;
#pragma unroll
        for (int nt = 0; nt < 4; nt++) {
            int cn = bn + wn + nt * 8 + 2 * qd;
            float b0 = bias[cn], b1 = bias[cn + 1];
            float2 v0 = make_float2(acc[mt][nt][0] + b0, acc[mt][nt][1] + b1);
            float2 v1 = make_float2(acc[mt][nt][2] + b0, acc[mt][nt][3] + b1);
            *(float2*)&C[(size_t)r0 * N + cn]       = v0;
            *(float2*)&C[(size_t)(r0 + 8) * N + cn] = v1;
        }
    }
}

// ---------------------------------------------------------------------------
// RoPE + split into head-major hi/lo half arrays. One thread = 2 d-elements.
// ---------------------------------------------------------------------------
__global__ __launch_bounds__(256) void rope_split_kernel(
    const float* __restrict__ qkv, const float* __restrict__ cosb,
    const float* __restrict__ sinb)
{
    int idx = blockIdx.x * 256 + threadIdx.x;   // MTOT*CDIM/2 of them
    int m  = idx >> 9;
    int p  = idx & 511;
    int h  = p >> 5;
    int dp = p & 31;
    int d0 = dp * 2;
    int b  = m >> 11;
    int s  = m & 2047;

    const float* row = qkv + (size_t)m * N3;
    int hd = h * 64 + d0;
    float cs0 = cosb[(size_t)m * 64 + d0], cs1 = cosb[(size_t)m * 64 + d0 + 1];
    float sn0 = sinb[(size_t)m * 64 + d0], sn1 = sinb[(size_t)m * 64 + d0 + 1];

    size_t o2 = (((size_t)(b * NHEADS + h) * SEQ) + s) * 32 + dp;   // half2 units
    unsigned hh, ll;

    // Q (scale 1/8 folded)
    {
        float x0 = row[hd], x1 = row[hd + 1];
        float r0 = (d0 < 32) ? -row[hd + 32] : row[hd - 32];
        float r1 = (d0 < 32) ? -row[hd + 33] : row[hd - 31];
        float q0 = (x0 * cs0 + r0 * sn0) * 0.125f;
        float q1 = (x1 * cs1 + r1 * sn1) * 0.125f;
        splitf(q0, q1, hh, ll);
        ((unsigned*)g_qh)[o2] = hh; ((unsigned*)g_ql)[o2] = ll;
    }
    // K
    {
        float x0 = row[CDIM + hd], x1 = row[CDIM + hd + 1];
        float r0 = (d0 < 32) ? -row[CDIM + hd + 32] : row[CDIM + hd - 32];
        float r1 = (d0 < 32) ? -row[CDIM + hd + 33] : row[CDIM + hd - 31];
        float k0 = x0 * cs0 + r0 * sn0;
        float k1 = x1 * cs1 + r1 * sn1;
        splitf(k0, k1, hh, ll);
        ((unsigned*)g_kh)[o2] = hh; ((unsigned*)g_kl)[o2] = ll;
    }
    // V
    {
        splitf(row[2 * CDIM + hd], row[2 * CDIM + hd + 1], hh, ll);
        ((unsigned*)g_vh)[o2] = hh; ((unsigned*)g_vl)[o2] = ll;
    }
}

// ---------------------------------------------------------------------------
// Flash attention, split-fp16 mma, cp.async double-buffered KV, ldmatrix.
// Block = 128 q rows, 8 warps x 16 q rows; KV tile 64.
// Smem (halves): Qh 0, Ql 8192; stage st at 16384+st*16384:
//   Kh +0, Kl +4096, Vh +8192, Vl +12288 (each 64x64; 128B rows,
//   XOR swizzle physSeg = seg ^ (row&7)).
// ---------------------------------------------------------------------------
#define A_STAGE 16384
#define ATTN_SMEM_BYTES ((16384 + 2 * A_STAGE) * 2)   // 96 KB

__device__ __forceinline__ void attn_kv_load(
    __half* sm, int st, size_t base, int t, int tid)
{
    __half* sb = sm + 16384 + st * A_STAGE;
#pragma unroll
    for (int i = 0; i < 2; i++) {
        int idx = tid + i * 256;
        int r = idx >> 3, s = idx & 7;
        unsigned off = r * 64 + ((s ^ (r & 7)) * 8);
        unsigned d = smem_u32(sb + off);
        size_t ga = base + (size_t)(t * 64 + r) * 64 + s * 8;
        cp16(d,             g_kh + ga);
        cp16(d + 4096 * 2,  g_kl + ga);
        cp16(d + 8192 * 2,  g_vh + ga);
        cp16(d + 12288 * 2, g_vl + ga);
    }
}

__global__ __launch_bounds__(256, 2) void attn_mma_kernel(float* __restrict__ dummy)
{
    extern __shared__ __half sm[];
    const int tid  = threadIdx.x;
    const int warp = tid >> 5, lane = tid & 31;
    const int g = lane >> 2, qd = lane & 3;
    const int ln15 = lane & 15, lhi = lane >> 4;
    const int qt = blockIdx.x;
    const int bh = blockIdx.y;
    const int b  = bh >> 4, h = bh & 15;
    const int q0 = warp * 16;

    size_t qbase  = ((size_t)bh * SEQ + (size_t)qt * 128) * HDIM;
    size_t kvbase = (size_t)bh * SEQ * HDIM;

    // prologue: Q + KV stage0 (group 0), KV stage1 (group 1)
#pragma unroll
    for (int i = 0; i < 4; i++) {
        int idx = tid + i * 256;
        int r = idx >> 3, s = idx & 7;
        unsigned off = r * 64 + ((s ^ (r & 7)) * 8);
        unsigned d = smem_u32(sm + off);
        size_t ga = qbase + (size_t)r * 64 + s * 8;
        cp16(d,            g_qh + ga);
        cp16(d + 8192 * 2, g_ql + ga);
    }
    attn_kv_load(sm, 0, kvbase, 0, tid);
    CP_COMMIT();
    attn_kv_load(sm, 1, kvbase, 1, tid);
    CP_COMMIT();

    float m0 = -1e30f, m1 = -1e30f, lsum0 = 0.f, lsum1 = 0.f;
    float o[8][4];
#pragma unroll
    for (int nt = 0; nt < 8; nt++)
#pragma unroll
        for (int i = 0; i < 4; i++) o[nt][i] = 0.f;

    const unsigned qbu = smem_u32(sm);

    int st = 0;
    for (int t = 0; t < SEQ / 64; t++, st ^= 1) {
        CP_WAIT1();
        __syncthreads();
        unsigned sbu = smem_u32(sm + 16384 + st * A_STAGE);

        // ---- S = Q K^T ----
        float sc[8][4];
#pragma unroll
        for (int nt = 0; nt < 8; nt++)
#pragma unroll
            for (int i = 0; i < 4; i++) sc[nt][i] = 0.f;

#pragma unroll
        for (int ks = 0; ks < 4; ks++) {
            int rq = q0 + ln15;
            int sA = 2 * ks + lhi;
            unsigned offq = rq * 64 + ((sA ^ (rq & 7)) * 8);
            unsigned ah[4], al[4];
            ldsm4(ah, qbu + offq * 2);
            ldsm4(al, qbu + (8192 + offq) * 2);
#pragma unroll
            for (int blk = 0; blk < 4; blk++) {
                int rk = blk * 16 + ln15;
                int sB = 2 * ks + lhi;
                unsigned offk = rk * 64 + ((sB ^ (rk & 7)) * 8);
                unsigned kh4[4], kl4[4];
                ldsm4(kh4, sbu + offk * 2);
                ldsm4(kl4, sbu + (4096 + offk) * 2);
                int nt = blk * 2;
                mma16(sc[nt], ah, kh4[0], kh4[2]);
                mma16(sc[nt], ah, kl4[0], kl4[2]);
                mma16(sc[nt], al, kh4[0], kh4[2]);
                mma16(sc[nt + 1], ah, kh4[1], kh4[3]);
                mma16(sc[nt + 1], ah, kl4[1], kl4[3]);
                mma16(sc[nt + 1], al, kh4[1], kh4[3]);
            }
        }

        // ---- online softmax (rows g, g+8; quad reduce) ----
        float mx0 = -1e30f, mx1 = -1e30f;
#pragma unroll
        for (int nt = 0; nt < 8; nt++) {
            mx0 = fmaxf(mx0, fmaxf(sc[nt][0], sc[nt][1]));
            mx1 = fmaxf(mx1, fmaxf(sc[nt][2], sc[nt][3]));
        }
        mx0 = fmaxf(mx0, __shfl_xor_sync(0xffffffffu, mx0, 1));
        mx0 = fmaxf(mx0, __shfl_xor_sync(0xffffffffu, mx0, 2));
        mx1 = fmaxf(mx1, __shfl_xor_sync(0xffffffffu, mx1, 1));
        mx1 = fmaxf(mx1, __shfl_xor_sync(0xffffffffu, mx1, 2));
        float nm0 = fmaxf(m0, mx0), nm1 = fmaxf(m1, mx1);
        float cr0 = __expf(m0 - nm0), cr1 = __expf(m1 - nm1);
        m0 = nm0; m1 = nm1;
        float rs0 = 0.f, rs1 = 0.f;
#pragma unroll
        for (int nt = 0; nt < 8; nt++) {
            sc[nt][0] = __expf(sc[nt][0] - nm0); rs0 += sc[nt][0];
            sc[nt][1] = __expf(sc[nt][1] - nm0); rs0 += sc[nt][1];
            sc[nt][2] = __expf(sc[nt][2] - nm1); rs1 += sc[nt][2];
            sc[nt][3] = __expf(sc[nt][3] - nm1); rs1 += sc[nt][3];
        }
        rs0 += __shfl_xor_sync(0xffffffffu, rs0, 1);
        rs0 += __shfl_xor_sync(0xffffffffu, rs0, 2);
        rs1 += __shfl_xor_sync(0xffffffffu, rs1, 1);
        rs1 += __shfl_xor_sync(0xffffffffu, rs1, 2);
        lsum0 = lsum0 * cr0 + rs0;
        lsum1 = lsum1 * cr1 + rs1;
#pragma unroll
        for (int nt = 0; nt < 8; nt++) {
            o[nt][0] *= cr0; o[nt][1] *= cr0;
            o[nt][2] *= cr1; o[nt][3] *= cr1;
        }

        // ---- O += P V  (P from registers; V via ldmatrix.trans) ----
#pragma unroll
        for (int j = 0; j < 4; j++) {
            unsigned ph[4], pl[4];
            splitf(sc[2 * j][0],     sc[2 * j][1],     ph[0], pl[0]);
            splitf(sc[2 * j][2],     sc[2 * j][3],     ph[1], pl[1]);
            splitf(sc[2 * j + 1][0], sc[2 * j + 1][1], ph[2], pl[2]);
            splitf(sc[2 * j + 1][2], sc[2 * j + 1][3], ph[3], pl[3]);
#pragma unroll
            for (int dbp = 0; dbp < 4; dbp++) {
                int rv = j * 16 + ((lane & 16) >> 1) + (lane & 7);
                int sV = dbp * 2 + ((lane >> 3) & 1);
                unsigned offv = rv * 64 + ((sV ^ (rv & 7)) * 8);
                unsigned vh4[4], vl4[4];
                ldsm4t(vh4, sbu + (8192 + offv) * 2);
                ldsm4t(vl4, sbu + (12288 + offv) * 2);
                int nt = dbp * 2;
                mma16(o[nt], ph, vh4[0], vh4[2]);
                mma16(o[nt], ph, vl4[0], vl4[2]);
                mma16(o[nt], pl, vh4[0], vh4[2]);
                mma16(o[nt + 1], ph, vh4[1], vh4[3]);
                mma16(o[nt + 1], ph, vl4[1], vl4[3]);
                mma16(o[nt + 1], pl, vh4[1], vh4[3]);
            }
        }

        __syncthreads();
        if (t + 2 < SEQ / 64)
            attn_kv_load(sm, st, kvbase, t + 2, tid);
        CP_COMMIT();
    }

    // ---- epilogue: normalize, split, write hi/lo halves [B,S,C] ----
    float inv0 = 1.f / lsum0, inv1 = 1.f / lsum1;
    int row0 = qt * 128 + q0 + g;
    size_t m_a = (size_t)(b * SEQ + row0);
    size_t m_b = m_a + 8;
#pragma unroll
    for (int nt = 0; nt < 8; nt++) {
        int col = h * HDIM + nt * 8 + 2 * qd;
        unsigned hh, ll;
        splitf(o[nt][0] * inv0, o[nt][1] * inv0, hh, ll);
        *(unsigned*)&g_attn_h[m_a * CDIM + col] = hh;
        *(unsigned*)&g_attn_l[m_a * CDIM + col] = ll;
        splitf(o[nt][2] * inv1, o[nt][3] * inv1, hh, ll);
        *(unsigned*)&g_attn_h[m_b * CDIM + col] = hh;
        *(unsigned*)&g_attn_l[m_b * CDIM + col] = ll;
    }
    (void)dummy;
}

// ---------------------------------------------------------------------------
// Launch
// ---------------------------------------------------------------------------
extern "C" void kernel_launch(void* const* d_in, const int* in_sizes, int n_in,
                              void* d_out, int out_size)
{
    const float* hidden = (const float*)d_in[0];
    const float* cosb   = (const float*)d_in[1];
    const float* sinb   = (const float*)d_in[2];
    const float* qkv_w  = (const float*)d_in[3];
    const float* qkv_b  = (const float*)d_in[4];
    const float* proj_w = (const float*)d_in[5];
    const float* proj_b = (const float*)d_in[6];
    float* out = (float*)d_out;

    float *p_qkv;
    __half *p_hid_h, *p_hid_l, *p_qw_h, *p_qw_l, *p_pw_h, *p_pw_l;
    __half *p_attn_h, *p_attn_l;
    cudaGetSymbolAddress((void**)&p_qkv,    g_qkv);
    cudaGetSymbolAddress((void**)&p_hid_h,  g_hid_h);
    cudaGetSymbolAddress((void**)&p_hid_l,  g_hid_l);
    cudaGetSymbolAddress((void**)&p_qw_h,   g_qkvw_h);
    cudaGetSymbolAddress((void**)&p_qw_l,   g_qkvw_l);
    cudaGetSymbolAddress((void**)&p_pw_h,   g_projw_h);
    cudaGetSymbolAddress((void**)&p_pw_l,   g_projw_l);
    cudaGetSymbolAddress((void**)&p_attn_h, g_attn_h);
    cudaGetSymbolAddress((void**)&p_attn_l, g_attn_l);

    cudaFuncSetAttribute(hgemm_nt_bias,
                         cudaFuncAttributeMaxDynamicSharedMemorySize,
                         G_SMEM_BYTES);
    cudaFuncSetAttribute(attn_mma_kernel,
                         cudaFuncAttributeMaxDynamicSharedMemorySize,
                         ATTN_SMEM_BYTES);

    // 0) split inputs to fp16 hi/lo
    split_kernel<<<(MTOT * CDIM / 4 + 255) / 256, 256>>>(hidden, p_hid_h, p_hid_l, MTOT * CDIM / 4);
    split_kernel<<<(N3 * CDIM / 4 + 255) / 256, 256>>>(qkv_w, p_qw_h, p_qw_l, N3 * CDIM / 4);
    split_kernel<<<(CDIM * CDIM / 4 + 255) / 256, 256>>>(proj_w, p_pw_h, p_pw_l, CDIM * CDIM / 4);

    // 1) QKV GEMM
    hgemm_nt_bias<<<dim3(N3 / 128, MTOT / 128), 256, G_SMEM_BYTES>>>(
        p_hid_h, p_hid_l, p_qw_h, p_qw_l, qkv_b, p_qkv, MTOT, N3, CDIM);

    // 2) RoPE + split to head-major hi/lo halves
    rope_split_kernel<<<(MTOT * CDIM / 2) / 256, 256>>>(p_qkv, cosb, sinb);

    // 3) Attention
    attn_mma_kernel<<<dim3(SEQ / 128, BATCH * NHEADS), 256, ATTN_SMEM_BYTES>>>(nullptr);

    // 4) Projection GEMM
    hgemm_nt_bias<<<dim3(CDIM / 128, MTOT / 128), 256, G_SMEM_BYTES>>>(
        p_attn_h, p_attn_l, p_pw_h, p_pw_l, proj_b, out, MTOT, CDIM, CDIM);
}